// round 16
// baseline (speedup 1.0000x reference)
#include <cuda_runtime.h>
#include <cuda_fp16.h>
#include <math.h>

#define BS   8
#define T_   32
#define C_   64
#define NN   4096
#define KK   32
#define DD   64
#define HH   64
#define FIN  320   // 5*D

// ---------------- persistent scratch (no allocation allowed) ----------------
__device__ __half  g_pmh[2][BS * NN * DD]; // double-buffered messages (fp16)
__device__ float   g_h [BS * NN * DD];     // hidden state (fp32, in-place)
__device__ float   g_ep[BS * NN * DD];     // eff_prim
__device__ float   g_ek[BS * NN * DD];     // eff_key
__device__ float   g_ed[BS * NN];          // eff_decay (scalar per b,n)
__device__ __half2 g_bwh[NN * 1024];       // fp16 branch weights (16.8 MB),
                                           // written by step0, read by steps 1-7

// fast sigmoid (precise-ish, for modk)
__device__ __forceinline__ float sigf(float x) {
    return __fdividef(1.f, 1.f + __expf(-x));
}
// fast tanh: 1 - 2/(e^{2x}+1).  Saturates correctly at +/-inf.  ~1e-6 rel.
__device__ __forceinline__ float tanhfast(float x) {
    const float e = __expf(2.f * x);
    return 1.f - __fdividef(2.f, e + 1.f);
}
// HW tanh (1 MUFU op).  Inner uses only; error damped before the output.
__device__ __forceinline__ float tanha(float x) {
    float y;
    asm("tanh.approx.f32 %0, %1;" : "=f"(y) : "f"(x));
    return y;
}
// sigmoid via HW tanh: 0.5 + 0.5*tanh(x/2)
__device__ __forceinline__ float sigt(float x) {
    return fmaf(tanha(0.5f * x), 0.5f, 0.5f);
}

// ---- packed f32x2 helpers (Blackwell) ----
typedef unsigned long long u64;
__device__ __forceinline__ u64 pk2(float lo, float hi) {
    u64 r;
    asm("mov.b64 %0, {%1, %2};" : "=l"(r) : "f"(lo), "f"(hi));
    return r;
}
__device__ __forceinline__ float2 upk2(u64 v) {
    float2 r;
    asm("mov.b64 {%0, %1}, %2;" : "=f"(r.x), "=f"(r.y) : "l"(v));
    return r;
}
__device__ __forceinline__ u64 fma2(u64 a, u64 b, u64 c) {
    u64 r;
    asm("fma.rn.f32x2 %0, %1, %2, %3;" : "=l"(r) : "l"(a), "l"(b), "l"(c));
    return r;
}

// butterfly multi-reduce: 8 sums over 32 lanes; lane l ends with sum for
// kk = (l>>2)&7.  Keep/send selects are the price of coalesced gathers
// (R13: removing them via swizzled gather decoalesced GMEM, -27%).
__device__ __forceinline__ float multireduce8(float v[8], int l) {
    const bool h16 = (l & 16);
    #pragma unroll
    for (int i = 0; i < 4; i++) {
        const float keep = h16 ? v[4 + i] : v[i];
        const float send = h16 ? v[i]     : v[4 + i];
        v[i] = keep + __shfl_xor_sync(0xffffffffu, send, 16);
    }
    const bool h8 = (l & 8);
    #pragma unroll
    for (int i = 0; i < 2; i++) {
        const float keep = h8 ? v[2 + i] : v[i];
        const float send = h8 ? v[i]     : v[2 + i];
        v[i] = keep + __shfl_xor_sync(0xffffffffu, send, 8);
    }
    const bool h4 = (l & 4);
    {
        const float keep = h4 ? v[1] : v[0];
        const float send = h4 ? v[0] : v[1];
        v[0] = keep + __shfl_xor_sync(0xffffffffu, send, 4);
    }
    v[0] += __shfl_xor_sync(0xffffffffu, v[0], 2);
    v[0] += __shfl_xor_sync(0xffffffffu, v[0], 1);
    return v[0];
}

// =============================================================================
// Kernel A: modulator MLP + state init.  One CTA per neuron n, 512 threads.
// DRAM-stream-bound — near its roof.  NO bw touch (R15 lesson: adding the bw
// conversion here costs +6us on the serial DRAM stream; step0 hides it).
// =============================================================================
__global__ void __launch_bounds__(512) modk(
    const float* __restrict__ h_in, const float* __restrict__ pm_in,
    const float* __restrict__ tp,   const float* __restrict__ tk,
    const float* __restrict__ prim, const float* __restrict__ keyp,
    const float* __restrict__ dlog, const float* __restrict__ fc1w,
    const float* __restrict__ fc1b, const float* __restrict__ fc2w,
    const float* __restrict__ fc2b, const float* __restrict__ mll)
{
    const int n   = blockIdx.x;
    const int tid = threadIdx.x;

    __shared__ __align__(16) float s_in[FIN * 12];      // [j][b] pad 12
    __shared__ float s_part[8 * 8 * 64];                // [seg][b][h]; tails reuse
    __shared__ float s_x[8 * 64];                       // tanh(fc1) activations
    __shared__ float s_o[24];                           // fc2 outputs [b][3]
    __shared__ float s_norm[16];                        // [b][{prim,key}]

    // ---- stage mod_input transposed: s_in[j*12 + b] ----
    for (int idx = tid; idx < BS * FIN; idx += 512) {
        const int b = idx / FIN, j = idx % FIN;
        float v;
        if      (j <  64) v = h_in[((size_t)b * NN + n) * DD + j];
        else if (j < 128) v = tp  [((size_t)b * NN + n) * DD + j - 64];
        else if (j < 192) v = tk  [((size_t)b * NN + n) * DD + j - 128];
        else if (j < 256) v = prim[(size_t)n * DD + j - 192];
        else              v = keyp[(size_t)n * DD + j - 256];
        s_in[j * 12 + b] = v;
    }
    __syncthreads();

    // ---- fc1: thread (seg,h), packed f32x2 over batch pairs ----
    {
        const int seg = tid >> 6, hh = tid & 63;
        u64 a[4] = {0ull, 0ull, 0ull, 0ull};
        const float* W = fc1w + (size_t)n * FIN * HH + hh;
        const int j0 = seg * 40;
        #pragma unroll 8
        for (int jj = 0; jj < 40; jj++) {
            const int j = j0 + jj;
            const float w = __ldcs(&W[(size_t)j * HH]);   // stream-once
            const u64 w2 = pk2(w, w);
            const u64* ip = (const u64*)&s_in[j * 12];
            a[0] = fma2(ip[0], w2, a[0]);
            a[1] = fma2(ip[1], w2, a[1]);
            a[2] = fma2(ip[2], w2, a[2]);
            a[3] = fma2(ip[3], w2, a[3]);
        }
        #pragma unroll
        for (int p = 0; p < 4; p++) {
            const float2 f = upk2(a[p]);
            s_part[((seg * 8) + 2 * p)     * 64 + hh] = f.x;
            s_part[((seg * 8) + 2 * p + 1) * 64 + hh] = f.y;
        }
    }
    __syncthreads();

    // ---- reduce segments, bias, tanh ----
    {
        const int b = tid >> 6, h = tid & 63;
        float s = 0.f;
        #pragma unroll
        for (int seg = 0; seg < 8; seg++) s += s_part[(seg * 8 + b) * 64 + h];
        s_x[b * 64 + h] = tanhfast(s + fc1b[(size_t)n * HH + h]);
    }
    __syncthreads();

    // ---- fc2 partials (192 threads) + norm partials (128 threads) ----
    if (tid < 192) {
        const int o = tid % 3, b = (tid / 3) & 7, hc = tid / 24;  // hc 0..7
        float acc = 0.f;
        #pragma unroll
        for (int i = 0; i < 8; i++) {
            const int h = hc * 8 + i;
            acc += s_x[b * 64 + h] * fc2w[((size_t)n * 64 + h) * 3 + o];
        }
        s_part[hc * 24 + b * 3 + o] = acc;
    } else if (tid < 320) {
        const int q = tid - 192;
        const int b = q >> 4, which = (q >> 3) & 1, dc = q & 7;
        float s = 0.f;
        const int base = 64 + which * 64 + dc * 8;
        #pragma unroll
        for (int i = 0; i < 8; i++) {
            const float v = s_in[(base + i) * 12 + b];
            s += v * v;
        }
        s_part[256 + (b * 2 + which) * 8 + dc] = s;
    }
    __syncthreads();

    // ---- final fc2 reduce (24 threads) + norm reduce (16 threads) ----
    if (tid < 24) {
        float acc = fc2b[(size_t)n * 3 + tid];
        #pragma unroll
        for (int hc = 0; hc < 8; hc++) acc += s_part[hc * 24 + tid];
        s_o[tid] = acc;
    } else if (tid >= 32 && tid < 48) {
        const int q = tid - 32;
        float s = 0.f;
        #pragma unroll
        for (int i = 0; i < 8; i++) s += s_part[256 + q * 8 + i];
        s_norm[q] = fmaxf(sqrtf(s), 1e-8f);
    }
    __syncthreads();

    // ---- finalize eff_* and init state ----
    {
        const int b = tid >> 6, d = tid & 63;
        const float mod_lr = sigf(mll[0]);
        const float gp = tanhfast(s_o[b * 3 + 0]);
        const float gk = tanhfast(s_o[b * 3 + 1]);
        const float dm = s_o[b * 3 + 2];
        const float tpv = s_in[(64 + d) * 12 + b];
        const float tkv = s_in[(128 + d) * 12 + b];
        const size_t off = ((size_t)b * NN + n) * DD + d;
        g_ep[off] = prim[(size_t)n * DD + d] + mod_lr * gp * (tpv / s_norm[b * 2 + 0]);
        g_ek[off] = keyp[(size_t)n * DD + d] + mod_lr * gk * (tkv / s_norm[b * 2 + 1]);
        g_h [off] = s_in[d * 12 + b];
        g_pmh[0][off] = __float2half_rn(pm_in[off]);
        if (d == 0) g_ed[(size_t)b * NN + n] = sigf(dlog[n] + dm);
    }
}

// =============================================================================
// Kernel B: one scan update.  R12 shape (validated 31.8 / 31.26us) with:
//  - cvt=1 (step0): fill smem bw from fp32 global AND write the fp16 image
//    (the STG overlaps step0's latency-bound gathers)
//  - cvt=0 (steps 1-7): fill from the image (1 LDG.128 + 1 STS.128/thread)
//  - gather offsets pre-multiplied (s_off[k] = conn[k]*32)
// Arithmetic bit-identical to R12/R15 (rel_err canary: 1.809677e-5).
// R13: gathers must stay warp-uniform in src.  R14: bw transpose doesn't help.
// R10: occupancy doesn't help.  R4: don't cap regs to 48.
// =============================================================================
__global__ void __launch_bounds__(256, 4) stepk(
    int parity, int t0, int cvt,
    const float* __restrict__ cc, const float* __restrict__ bw,
    const float* __restrict__ gw, const int* __restrict__ conn,
    float* __restrict__ out)
{
    __shared__ __half2 s_bwh[1024];   // [k][d/2]  fp16 branch weights
    __shared__ float   s_gw[256];     // [nb][d]   fp32 group weights
    __shared__ int     s_off[32];     // conn[k]*32 (half2-word offsets)

    const int n   = blockIdx.x;
    const int tid = threadIdx.x;
    const int b   = tid >> 5;
    const int l   = tid & 31;

    const __half* pm_in  = g_pmh[parity];
    __half*       pm_out = g_pmh[parity ^ 1];

    if (cvt) {
        // step0: fp32 bw -> fp16 smem + persistent image for steps 1-7
        #pragma unroll
        for (int i = 0; i < 2; i++) {
            const int idx = tid + 256 * i;                  // float4 index, 0..511
            const float4 v = __ldg(&((const float4*)(bw + (size_t)n * 2048))[idx]);
            const __half2 h0 = __floats2half2_rn(v.x, v.y);
            const __half2 h1 = __floats2half2_rn(v.z, v.w);
            s_bwh[2 * idx]     = h0;
            s_bwh[2 * idx + 1] = h1;
            uint2 pk;
            pk.x = *(const unsigned int*)&h0;
            pk.y = *(const unsigned int*)&h1;
            ((uint2*)(g_bwh + (size_t)n * 1024))[idx] = pk;
        }
    } else {
        ((uint4*)s_bwh)[tid] = __ldg(&((const uint4*)(g_bwh + (size_t)n * 1024))[tid]);
    }
    s_gw[tid] = gw[(size_t)n * 256 + tid];
    if (tid < 32) s_off[tid] = conn[(size_t)n * KK + tid] * 32;

    const size_t off = ((size_t)b * NN + n) * DD;
    const float2 key = *(const float2*)&g_ek[off + 2 * l];
    __syncthreads();

    const __half2* pmb = (const __half2*)(pm_in + (size_t)b * NN * DD);
    __half2 accp[4];

    __half2 m[8];
    #pragma unroll
    for (int kk = 0; kk < 8; kk++)
        m[kk] = __ldg(&pmb[s_off[kk] + l]);

    #pragma unroll
    for (int c = 0; c < 4; c++) {
        // ---- phase 1: fp32 sim partials + half2 premul t = m*bw ----
        float v[8];
        __half2 t[8];
        #pragma unroll
        for (int kk = 0; kk < 8; kk++) {
            const float2 mf = __half22float2(m[kk]);
            v[kk] = key.x * mf.x + key.y * mf.y;
            t[kk] = __hmul2(m[kk], s_bwh[(c * 8 + kk) * 32 + l]);
        }

        // ---- phase 2: prefetch next chunk (overlaps reduce + accumulate) ----
        if (c < 3) {
            #pragma unroll
            for (int kk = 0; kk < 8; kk++)
                m[kk] = __ldg(&pmb[s_off[(c + 1) * 8 + kk] + l]);
        }

        // ---- phase 3: fp32 butterfly multi-reduce -> sigmoid ----
        const float w = sigt(multireduce8(v, l));
        const __half2 w2 = __float2half2_rn(w);

        // ---- phase 4: half2 accumulate (chunk c == branch c) ----
        __half2 a = __float2half2_rn(0.f);
        #pragma unroll
        for (int kk = 0; kk < 8; kk++) {
            const __half2 wk2 = __shfl_sync(0xffffffffu, w2, kk << 2);
            a = __hfma2(t[kk], wk2, a);
        }
        accp[c] = a;
    }

    // ---- branch tanh (HW) -> group sum -> group tanh (HW, damped) ----
    float r0 = 0.f, r1 = 0.f;
    #pragma unroll
    for (int nb = 0; nb < 4; nb++) {
        const float2 av  = __half22float2(accp[nb]);
        const float2 gwv = *(const float2*)&s_gw[nb * 64 + 2 * l];
        r0 += tanha(av.x) * gwv.x;
        r1 += tanha(av.y) * gwv.y;
    }
    r0 = tanha(r0);
    r1 = tanha(r1);

    if (n < C_) {   // cc injection on first C neurons
        const float2 ccv = *(const float2*)&cc[(((size_t)b * T_ + t0) * C_ + n) * DD + 2 * l];
        r0 += ccv.x;
        r1 += ccv.y;
    }

    // ---- h / message update (fp32; output-facing tanh stays precise) ----
    const float ed = g_ed[(size_t)b * NN + n];
    const float2 h = *(const float2*)&g_h[off + 2 * l];
    const float nh0 = ed * h.x + (1.f - ed) * r0;
    const float nh1 = ed * h.y + (1.f - ed) * r1;
    *(float2*)&g_h[off + 2 * l] = make_float2(nh0, nh1);
    const float2 ep = *(const float2*)&g_ep[off + 2 * l];
    const float p0 = tanhfast(nh0 * ep.x);
    const float p1 = tanhfast(nh1 * ep.y);
    *((__half2*)(pm_out + off) + l) = __floats2half2_rn(p0, p1);

    if (n < C_) {   // emit the 4 timesteps this update covers (fp32 output)
        #pragma unroll
        for (int tt = 0; tt < 4; tt++) {
            const size_t oo = (((size_t)b * T_ + t0 + tt) * C_ + n) * DD + 2 * l;
            *(float2*)&out[oo] = make_float2(p0, p1);
        }
    }
}

// =============================================================================
extern "C" void kernel_launch(void* const* d_in, const int* in_sizes, int n_in,
                              void* d_out, int out_size)
{
    const float* cc    = (const float*)d_in[0];
    const float* h_in  = (const float*)d_in[1];
    const float* pm_in = (const float*)d_in[2];
    const float* tp    = (const float*)d_in[3];
    const float* tk    = (const float*)d_in[4];
    const float* prim  = (const float*)d_in[5];
    const float* keyp  = (const float*)d_in[6];
    const float* dlog  = (const float*)d_in[7];
    const float* bw    = (const float*)d_in[8];
    const float* gw    = (const float*)d_in[9];
    const float* fc1w  = (const float*)d_in[10];
    const float* fc1b  = (const float*)d_in[11];
    const float* fc2w  = (const float*)d_in[12];
    const float* fc2b  = (const float*)d_in[13];
    const float* mll   = (const float*)d_in[14];
    const int*   conn  = (const int*)d_in[15];
    float* out = (float*)d_out;

    modk<<<NN, 512>>>(h_in, pm_in, tp, tk, prim, keyp, dlog,
                      fc1w, fc1b, fc2w, fc2b, mll);

    // stride = 4 (fixed by setup): updates at t = 0,4,...,28; output replicated x4
    // step0 (cvt=1) converts bw -> fp16 image; steps 1-7 consume it.
    for (int u = 0; u < 8; u++) {
        stepk<<<NN, 256>>>(u & 1, 4 * u, (u == 0) ? 1 : 0, cc, bw, gw, conn, out);
    }
}

// round 17
// speedup vs baseline: 1.0299x; 1.0299x over previous
#include <cuda_runtime.h>
#include <cuda_fp16.h>
#include <math.h>

#define BS   8
#define T_   32
#define C_   64
#define NN   4096
#define KK   32
#define DD   64
#define HH   64
#define FIN  320   // 5*D

// ---------------- persistent scratch (no allocation allowed) ----------------
__device__ __half  g_pmh[2][BS * NN * DD]; // double-buffered messages (fp16)
__device__ float   g_h [BS * NN * DD];     // hidden state (fp32, in-place)
__device__ float   g_ep[BS * NN * DD];     // eff_prim
__device__ float   g_ek[BS * NN * DD];     // eff_key
__device__ float   g_ed[BS * NN];          // eff_decay (scalar per b,n)
__device__ __half2 g_bwh[NN * 1024];       // fp16 branch weights (16.8 MB),
                                           // written by stepk0, read by stepk

// fast sigmoid (precise-ish, for modk)
__device__ __forceinline__ float sigf(float x) {
    return __fdividef(1.f, 1.f + __expf(-x));
}
// fast tanh: 1 - 2/(e^{2x}+1).  Saturates correctly at +/-inf.  ~1e-6 rel.
__device__ __forceinline__ float tanhfast(float x) {
    const float e = __expf(2.f * x);
    return 1.f - __fdividef(2.f, e + 1.f);
}
// HW tanh (1 MUFU op).  Inner uses only; error damped before the output.
__device__ __forceinline__ float tanha(float x) {
    float y;
    asm("tanh.approx.f32 %0, %1;" : "=f"(y) : "f"(x));
    return y;
}
// sigmoid via HW tanh: 0.5 + 0.5*tanh(x/2)
__device__ __forceinline__ float sigt(float x) {
    return fmaf(tanha(0.5f * x), 0.5f, 0.5f);
}

// ---- packed f32x2 helpers (Blackwell) ----
typedef unsigned long long u64;
__device__ __forceinline__ u64 pk2(float lo, float hi) {
    u64 r;
    asm("mov.b64 %0, {%1, %2};" : "=l"(r) : "f"(lo), "f"(hi));
    return r;
}
__device__ __forceinline__ float2 upk2(u64 v) {
    float2 r;
    asm("mov.b64 {%0, %1}, %2;" : "=f"(r.x), "=f"(r.y) : "l"(v));
    return r;
}
__device__ __forceinline__ u64 fma2(u64 a, u64 b, u64 c) {
    u64 r;
    asm("fma.rn.f32x2 %0, %1, %2, %3;" : "=l"(r) : "l"(a), "l"(b), "l"(c));
    return r;
}

// butterfly multi-reduce: 8 sums over 32 lanes; lane l ends with sum for
// kk = (l>>2)&7.  Keep/send selects are the price of coalesced gathers
// (R13: removing them via swizzled gather decoalesced GMEM, -27%).
__device__ __forceinline__ float multireduce8(float v[8], int l) {
    const bool h16 = (l & 16);
    #pragma unroll
    for (int i = 0; i < 4; i++) {
        const float keep = h16 ? v[4 + i] : v[i];
        const float send = h16 ? v[i]     : v[4 + i];
        v[i] = keep + __shfl_xor_sync(0xffffffffu, send, 16);
    }
    const bool h8 = (l & 8);
    #pragma unroll
    for (int i = 0; i < 2; i++) {
        const float keep = h8 ? v[2 + i] : v[i];
        const float send = h8 ? v[i]     : v[2 + i];
        v[i] = keep + __shfl_xor_sync(0xffffffffu, send, 8);
    }
    const bool h4 = (l & 4);
    {
        const float keep = h4 ? v[1] : v[0];
        const float send = h4 ? v[0] : v[1];
        v[0] = keep + __shfl_xor_sync(0xffffffffu, send, 4);
    }
    v[0] += __shfl_xor_sync(0xffffffffu, v[0], 2);
    v[0] += __shfl_xor_sync(0xffffffffu, v[0], 1);
    return v[0];
}

// ---- shared step body (inlined into both step kernels) --------------------
// FILL_IMAGE is a compile-time flag: stepk0 reads fp32 bw + writes the fp16
// image; stepk reads the image.  Separate __global__ wrappers keep each
// step kernel's compiled prologue minimal (R16: a runtime cvt branch cost
// +2.6us on EVERY step).
template <bool FILL_IMAGE>
__device__ __forceinline__ void step_body(
    int parity, int t0,
    const float* __restrict__ cc, const float* __restrict__ bw,
    const float* __restrict__ gw, const int* __restrict__ conn,
    float* __restrict__ out)
{
    __shared__ __half2 s_bwh[1024];   // [k][d/2]  fp16 branch weights
    __shared__ float   s_gw[256];     // [nb][d]   fp32 group weights
    __shared__ int     s_off[32];     // conn[k]*32 (half2-word offsets)

    const int n   = blockIdx.x;
    const int tid = threadIdx.x;
    const int b   = tid >> 5;
    const int l   = tid & 31;

    const __half* pm_in  = g_pmh[parity];
    __half*       pm_out = g_pmh[parity ^ 1];

    if (FILL_IMAGE) {
        // step0: fp32 bw -> fp16 smem + persistent image for later steps
        #pragma unroll
        for (int i = 0; i < 2; i++) {
            const int idx = tid + 256 * i;                  // float4 index 0..511
            const float4 v = __ldg(&((const float4*)(bw + (size_t)n * 2048))[idx]);
            const __half2 h0 = __floats2half2_rn(v.x, v.y);
            const __half2 h1 = __floats2half2_rn(v.z, v.w);
            s_bwh[2 * idx]     = h0;
            s_bwh[2 * idx + 1] = h1;
            uint2 pk;
            pk.x = *(const unsigned int*)&h0;
            pk.y = *(const unsigned int*)&h1;
            ((uint2*)(g_bwh + (size_t)n * 1024))[idx] = pk;
        }
    } else {
        ((uint4*)s_bwh)[tid] = __ldg(&((const uint4*)(g_bwh + (size_t)n * 1024))[tid]);
    }
    s_gw[tid] = gw[(size_t)n * 256 + tid];
    if (tid < 32) s_off[tid] = conn[(size_t)n * KK + tid] * 32;

    const size_t off = ((size_t)b * NN + n) * DD;
    const float2 key = *(const float2*)&g_ek[off + 2 * l];
    __syncthreads();

    const __half2* pmb = (const __half2*)(pm_in + (size_t)b * NN * DD);
    __half2 accp[4];

    __half2 m[8];
    #pragma unroll
    for (int kk = 0; kk < 8; kk++)
        m[kk] = __ldg(&pmb[s_off[kk] + l]);

    #pragma unroll
    for (int c = 0; c < 4; c++) {
        // ---- phase 1: fp32 sim partials + half2 premul t = m*bw ----
        float v[8];
        __half2 t[8];
        #pragma unroll
        for (int kk = 0; kk < 8; kk++) {
            const float2 mf = __half22float2(m[kk]);
            v[kk] = key.x * mf.x + key.y * mf.y;
            t[kk] = __hmul2(m[kk], s_bwh[(c * 8 + kk) * 32 + l]);
        }

        // ---- phase 2: prefetch next chunk (overlaps reduce + accumulate) ----
        if (c < 3) {
            #pragma unroll
            for (int kk = 0; kk < 8; kk++)
                m[kk] = __ldg(&pmb[s_off[(c + 1) * 8 + kk] + l]);
        }

        // ---- phase 3: fp32 butterfly multi-reduce -> sigmoid ----
        const float w = sigt(multireduce8(v, l));
        const __half2 w2 = __float2half2_rn(w);

        // ---- phase 4: half2 accumulate (chunk c == branch c) ----
        __half2 a = __float2half2_rn(0.f);
        #pragma unroll
        for (int kk = 0; kk < 8; kk++) {
            const __half2 wk2 = __shfl_sync(0xffffffffu, w2, kk << 2);
            a = __hfma2(t[kk], wk2, a);
        }
        accp[c] = a;
    }

    // ---- branch tanh (HW) -> group sum -> group tanh (HW, damped) ----
    float r0 = 0.f, r1 = 0.f;
    #pragma unroll
    for (int nb = 0; nb < 4; nb++) {
        const float2 av  = __half22float2(accp[nb]);
        const float2 gwv = *(const float2*)&s_gw[nb * 64 + 2 * l];
        r0 += tanha(av.x) * gwv.x;
        r1 += tanha(av.y) * gwv.y;
    }
    r0 = tanha(r0);
    r1 = tanha(r1);

    if (n < C_) {   // cc injection on first C neurons
        const float2 ccv = *(const float2*)&cc[(((size_t)b * T_ + t0) * C_ + n) * DD + 2 * l];
        r0 += ccv.x;
        r1 += ccv.y;
    }

    // ---- h / message update (fp32; output-facing tanh stays precise) ----
    const float ed = g_ed[(size_t)b * NN + n];
    const float2 h = *(const float2*)&g_h[off + 2 * l];
    const float nh0 = ed * h.x + (1.f - ed) * r0;
    const float nh1 = ed * h.y + (1.f - ed) * r1;
    *(float2*)&g_h[off + 2 * l] = make_float2(nh0, nh1);
    const float2 ep = *(const float2*)&g_ep[off + 2 * l];
    const float p0 = tanhfast(nh0 * ep.x);
    const float p1 = tanhfast(nh1 * ep.y);
    *((__half2*)(pm_out + off) + l) = __floats2half2_rn(p0, p1);

    if (n < C_) {   // emit the 4 timesteps this update covers (fp32 output)
        #pragma unroll
        for (int tt = 0; tt < 4; tt++) {
            const size_t oo = (((size_t)b * T_ + t0 + tt) * C_ + n) * DD + 2 * l;
            *(float2*)&out[oo] = make_float2(p0, p1);
        }
    }
}

// step0: converts bw and seeds the fp16 image
__global__ void __launch_bounds__(256, 4) stepk0(
    const float* __restrict__ cc, const float* __restrict__ bw,
    const float* __restrict__ gw, const int* __restrict__ conn,
    float* __restrict__ out)
{
    step_body<true>(0, 0, cc, bw, gw, conn, out);
}

// steps 1-7: consume the fp16 image (exact R15 data path)
__global__ void __launch_bounds__(256, 4) stepk(
    int parity, int t0,
    const float* __restrict__ cc, const float* __restrict__ gw,
    const int* __restrict__ conn, float* __restrict__ out)
{
    step_body<false>(parity, t0, cc, nullptr, gw, conn, out);
}

// =============================================================================
// Kernel A: modulator MLP + state init.  One CTA per neuron n, 512 threads.
// DRAM-stream-bound — near its roof.  NO bw touch (R15: conversion here costs
// +6us on the serial DRAM stream; step0 hides it instead).
// =============================================================================
__global__ void __launch_bounds__(512) modk(
    const float* __restrict__ h_in, const float* __restrict__ pm_in,
    const float* __restrict__ tp,   const float* __restrict__ tk,
    const float* __restrict__ prim, const float* __restrict__ keyp,
    const float* __restrict__ dlog, const float* __restrict__ fc1w,
    const float* __restrict__ fc1b, const float* __restrict__ fc2w,
    const float* __restrict__ fc2b, const float* __restrict__ mll)
{
    const int n   = blockIdx.x;
    const int tid = threadIdx.x;

    __shared__ __align__(16) float s_in[FIN * 12];      // [j][b] pad 12
    __shared__ float s_part[8 * 8 * 64];                // [seg][b][h]; tails reuse
    __shared__ float s_x[8 * 64];                       // tanh(fc1) activations
    __shared__ float s_o[24];                           // fc2 outputs [b][3]
    __shared__ float s_norm[16];                        // [b][{prim,key}]

    // ---- stage mod_input transposed: s_in[j*12 + b] ----
    for (int idx = tid; idx < BS * FIN; idx += 512) {
        const int b = idx / FIN, j = idx % FIN;
        float v;
        if      (j <  64) v = h_in[((size_t)b * NN + n) * DD + j];
        else if (j < 128) v = tp  [((size_t)b * NN + n) * DD + j - 64];
        else if (j < 192) v = tk  [((size_t)b * NN + n) * DD + j - 128];
        else if (j < 256) v = prim[(size_t)n * DD + j - 192];
        else              v = keyp[(size_t)n * DD + j - 256];
        s_in[j * 12 + b] = v;
    }
    __syncthreads();

    // ---- fc1: thread (seg,h), packed f32x2 over batch pairs ----
    {
        const int seg = tid >> 6, hh = tid & 63;
        u64 a[4] = {0ull, 0ull, 0ull, 0ull};
        const float* W = fc1w + (size_t)n * FIN * HH + hh;
        const int j0 = seg * 40;
        #pragma unroll 8
        for (int jj = 0; jj < 40; jj++) {
            const int j = j0 + jj;
            const float w = __ldcs(&W[(size_t)j * HH]);   // stream-once
            const u64 w2 = pk2(w, w);
            const u64* ip = (const u64*)&s_in[j * 12];
            a[0] = fma2(ip[0], w2, a[0]);
            a[1] = fma2(ip[1], w2, a[1]);
            a[2] = fma2(ip[2], w2, a[2]);
            a[3] = fma2(ip[3], w2, a[3]);
        }
        #pragma unroll
        for (int p = 0; p < 4; p++) {
            const float2 f = upk2(a[p]);
            s_part[((seg * 8) + 2 * p)     * 64 + hh] = f.x;
            s_part[((seg * 8) + 2 * p + 1) * 64 + hh] = f.y;
        }
    }
    __syncthreads();

    // ---- reduce segments, bias, tanh ----
    {
        const int b = tid >> 6, h = tid & 63;
        float s = 0.f;
        #pragma unroll
        for (int seg = 0; seg < 8; seg++) s += s_part[(seg * 8 + b) * 64 + h];
        s_x[b * 64 + h] = tanhfast(s + fc1b[(size_t)n * HH + h]);
    }
    __syncthreads();

    // ---- fc2 partials (192 threads) + norm partials (128 threads) ----
    if (tid < 192) {
        const int o = tid % 3, b = (tid / 3) & 7, hc = tid / 24;  // hc 0..7
        float acc = 0.f;
        #pragma unroll
        for (int i = 0; i < 8; i++) {
            const int h = hc * 8 + i;
            acc += s_x[b * 64 + h] * fc2w[((size_t)n * 64 + h) * 3 + o];
        }
        s_part[hc * 24 + b * 3 + o] = acc;
    } else if (tid < 320) {
        const int q = tid - 192;
        const int b = q >> 4, which = (q >> 3) & 1, dc = q & 7;
        float s = 0.f;
        const int base = 64 + which * 64 + dc * 8;
        #pragma unroll
        for (int i = 0; i < 8; i++) {
            const float v = s_in[(base + i) * 12 + b];
            s += v * v;
        }
        s_part[256 + (b * 2 + which) * 8 + dc] = s;
    }
    __syncthreads();

    // ---- final fc2 reduce (24 threads) + norm reduce (16 threads) ----
    if (tid < 24) {
        float acc = fc2b[(size_t)n * 3 + tid];
        #pragma unroll
        for (int hc = 0; hc < 8; hc++) acc += s_part[hc * 24 + tid];
        s_o[tid] = acc;
    } else if (tid >= 32 && tid < 48) {
        const int q = tid - 32;
        float s = 0.f;
        #pragma unroll
        for (int i = 0; i < 8; i++) s += s_part[256 + q * 8 + i];
        s_norm[q] = fmaxf(sqrtf(s), 1e-8f);
    }
    __syncthreads();

    // ---- finalize eff_* and init state ----
    {
        const int b = tid >> 6, d = tid & 63;
        const float mod_lr = sigf(mll[0]);
        const float gp = tanhfast(s_o[b * 3 + 0]);
        const float gk = tanhfast(s_o[b * 3 + 1]);
        const float dm = s_o[b * 3 + 2];
        const float tpv = s_in[(64 + d) * 12 + b];
        const float tkv = s_in[(128 + d) * 12 + b];
        const size_t off = ((size_t)b * NN + n) * DD + d;
        g_ep[off] = prim[(size_t)n * DD + d] + mod_lr * gp * (tpv / s_norm[b * 2 + 0]);
        g_ek[off] = keyp[(size_t)n * DD + d] + mod_lr * gk * (tkv / s_norm[b * 2 + 1]);
        g_h [off] = s_in[d * 12 + b];
        g_pmh[0][off] = __float2half_rn(pm_in[off]);
        if (d == 0) g_ed[(size_t)b * NN + n] = sigf(dlog[n] + dm);
    }
}

// =============================================================================
extern "C" void kernel_launch(void* const* d_in, const int* in_sizes, int n_in,
                              void* d_out, int out_size)
{
    const float* cc    = (const float*)d_in[0];
    const float* h_in  = (const float*)d_in[1];
    const float* pm_in = (const float*)d_in[2];
    const float* tp    = (const float*)d_in[3];
    const float* tk    = (const float*)d_in[4];
    const float* prim  = (const float*)d_in[5];
    const float* keyp  = (const float*)d_in[6];
    const float* dlog  = (const float*)d_in[7];
    const float* bw    = (const float*)d_in[8];
    const float* gw    = (const float*)d_in[9];
    const float* fc1w  = (const float*)d_in[10];
    const float* fc1b  = (const float*)d_in[11];
    const float* fc2w  = (const float*)d_in[12];
    const float* fc2b  = (const float*)d_in[13];
    const float* mll   = (const float*)d_in[14];
    const int*   conn  = (const int*)d_in[15];
    float* out = (float*)d_out;

    modk<<<NN, 512>>>(h_in, pm_in, tp, tk, prim, keyp, dlog,
                      fc1w, fc1b, fc2w, fc2b, mll);

    // stride = 4 (fixed by setup): updates at t = 0,4,...,28; replicated x4.
    // step0 converts bw -> fp16 image; steps 1-7 consume it.
    stepk0<<<NN, 256>>>(cc, bw, gw, conn, out);
    for (int u = 1; u < 8; u++) {
        stepk<<<NN, 256>>>(u & 1, 4 * u, cc, gw, conn, out);
    }
}